// round 4
// baseline (speedup 1.0000x reference)
#include <cuda_runtime.h>
#include <cstdint>

// Output = constant 1.0f, [32,128,4096] fp32 = 64 MiB (L2-resident write stream).
// STG path saturates at ~5.9 TB/s (= ~50% L2 SOL) regardless of launch shape
// (R1-R3). Experiment: TMA bulk stores (UBLKCP) -- SMEM->global full-line
// writes from the TMA engine, bypassing the L1tex store-wavefront path.
// 256 CTAs x 256 KiB each; per CTA: fill 32 KiB SMEM with ones once, then
// 8 async bulk stores of 32 KiB, commit + wait before exit.

__device__ __forceinline__ uint32_t smem_u32(const void* p) {
    uint32_t a;
    asm("{ .reg .u64 t; cvta.to.shared.u64 t, %1; cvt.u32.u64 %0, t; }"
        : "=r"(a) : "l"(p));
    return a;
}

__global__ __launch_bounds__(128) void fill_ones_tma(float* __restrict__ out) {
    __shared__ alignas(128) float buf[8192];  // 32 KiB of ones

    const float4 v = make_float4(1.0f, 1.0f, 1.0f, 1.0f);
    float4* b4 = reinterpret_cast<float4*>(buf);
    #pragma unroll
    for (int k = 0; k < 16; k++)              // 8192/4 = 2048 float4 / 128 thr
        b4[threadIdx.x + k * 128] = v;
    __syncthreads();
    asm volatile("fence.proxy.async.shared::cta;" ::: "memory");

    if (threadIdx.x == 0) {
        uint32_t saddr = smem_u32(buf);
        float* base = out + (size_t)blockIdx.x * 65536;  // 64Ki floats = 256 KiB
        #pragma unroll
        for (int k = 0; k < 8; k++) {
            asm volatile(
                "cp.async.bulk.global.shared::cta.bulk_group [%0], [%1], %2;"
                :: "l"(base + (size_t)k * 8192), "r"(saddr), "n"(32768)
                : "memory");
        }
        asm volatile("cp.async.bulk.commit_group;" ::: "memory");
        asm volatile("cp.async.bulk.wait_group 0;" ::: "memory");
    }
}

extern "C" void kernel_launch(void* const* d_in, const int* in_sizes, int n_in,
                              void* d_out, int out_size) {
    (void)d_in; (void)in_sizes; (void)n_in; (void)out_size;
    // 16777216 floats = 256 blocks * 65536 floats (256 KiB per block)
    fill_ones_tma<<<256, 128>>>(reinterpret_cast<float*>(d_out));
}

// round 5
// speedup vs baseline: 1.1544x; 1.1544x over previous
#include <cuda_runtime.h>
#include <cstdint>

// Output = constant 1.0f, [32,128,4096] fp32 = 64 MiB, L2-resident write stream.
// Established across R1-R4: the L2 write port caps at ~5.9 TB/s (~50% L2 SOL)
// regardless of path (STG shapes and TMA bulk store all land 11.4-13.1us ncu);
// floor = 64MiB / 5.9TB/s ~= 10.8us. This shape targets the floor exactly:
//  - 1024 blocks x 256 thr -> 8 CTAs/SM residency => single wave (1184 slots)
//  - 16 independent unrolled STG.E.128 per thread (deep store ILP)
//  - warp-contiguous 512B segments, full-line L2 writes

__global__ __launch_bounds__(256) void fill_ones_kernel(float4* __restrict__ out) {
    const float4 v = make_float4(1.0f, 1.0f, 1.0f, 1.0f);
    // Block owns 256*16 = 4096 consecutive float4 (64 KiB).
    float4* p = out + (size_t)blockIdx.x * 4096 + threadIdx.x;
    #pragma unroll
    for (int k = 0; k < 16; k++) {
        p[k * 256] = v;
    }
}

extern "C" void kernel_launch(void* const* d_in, const int* in_sizes, int n_in,
                              void* d_out, int out_size) {
    (void)d_in; (void)in_sizes; (void)n_in; (void)out_size;
    // 16777216 floats = 4194304 float4 = 1024 blocks * 256 thr * 16
    fill_ones_kernel<<<1024, 256>>>(reinterpret_cast<float4*>(d_out));
}

// round 7
// speedup vs baseline: 1.1775x; 1.0200x over previous
#include <cuda_runtime.h>
#include <cstdint>

// Final kernel. Output = constant 1.0f everywhere, [32,128,4096] fp32 = 64 MiB
// (reference's quantum-circuit ops are identity stubs; probs.sum() == 1.0).
//
// Measured conclusion (R1-R5): this is an L2-resident write stream pinned at
// the L2 write-port ceiling (~5.9 TB/s, ~50% L2 SOL), path-independent (STG
// in 4 shapes and TMA bulk store all land 11.4-13.1us ncu). Floor ~10.8us.
// This shape (2048 x 256 x 8 unrolled STG.E.128, 32 KiB per CTA) was the
// empirically fastest: ncu 11.39us, harness 12.77us -- ~95% of the HW floor.

__global__ __launch_bounds__(256) void fill_ones_kernel(float4* __restrict__ out) {
    const float4 v = make_float4(1.0f, 1.0f, 1.0f, 1.0f);
    // Each block owns 256*8 = 2048 consecutive float4 (32 KiB).
    // Thread t writes block_base + t + k*256: every warp store is a
    // contiguous 512B segment -> full-line L2 writes.
    float4* p = out + (size_t)blockIdx.x * 2048 + threadIdx.x;
    #pragma unroll
    for (int k = 0; k < 8; k++) {
        p[k * 256] = v;
    }
}

extern "C" void kernel_launch(void* const* d_in, const int* in_sizes, int n_in,
                              void* d_out, int out_size) {
    (void)d_in; (void)in_sizes; (void)n_in; (void)out_size;
    // 16777216 floats = 4194304 float4 = 2048 blocks * 256 thr * 8
    fill_ones_kernel<<<2048, 256>>>(reinterpret_cast<float4*>(d_out));
}